// round 5
// baseline (speedup 1.0000x reference)
#include <cuda_runtime.h>
#include <cuda_bf16.h>
#include <math.h>
#include <stdint.h>

// ---------------- problem constants ----------------
#define Tt   40
#define Ll   91
#define Cc   512
#define BQn  14400
#define BTn  640
#define MPAD 14592            // 57 * 256

// ---------------- GEMM tiling ----------------
#define BM 256
#define BN 128
#define BK 64                 // bf16 per chunk (128 bytes per row)
#define NCH 8                 // Cc / BK
#define STAGES 3
#define A_BYTES 32768         // 256 x 128B
#define STAGE_BYTES 49152     // A 32KB + B 16KB
#define DYNSMEM (STAGES * STAGE_BYTES)

#define FEAT_BLOCKS 3600      // BQn*Cc/8/256

// ---------------- scratch (zero-initialized device globals) ----------------
__device__ __nv_bfloat16 g_A[(size_t)MPAD * Cc];   // focal features (pad rows stay zero)
__device__ __nv_bfloat16 g_B[(size_t)BTn * Cc];    // normalized label-map rows
__device__ float         g_tbox[BTn * 8];          // cx,cy,w,h,x0,y0,x1,y1

// ---------------- helpers ----------------
__device__ __forceinline__ uint32_t cvta_s(const void* p) {
    uint32_t a;
    asm("{ .reg .u64 t; cvta.to.shared.u64 t, %1; cvt.u32.u64 %0, t; }"
        : "=r"(a) : "l"(p));
    return a;
}

#define CP16(dst, src) asm volatile("cp.async.cg.shared.global [%0], [%1], 16;" :: "r"(dst), "l"(src))
#define CPCOMMIT()     asm volatile("cp.async.commit_group;")
#define CPWAIT(n)      asm volatile("cp.async.wait_group %0;" :: "n"(n))

__device__ __forceinline__ void ldsm4(uint32_t& r0, uint32_t& r1, uint32_t& r2,
                                      uint32_t& r3, uint32_t addr) {
    asm volatile("ldmatrix.sync.aligned.m8n8.x4.shared.b16 {%0,%1,%2,%3}, [%4];"
                 : "=r"(r0), "=r"(r1), "=r"(r2), "=r"(r3) : "r"(addr));
}

__device__ __forceinline__ void mma_bf16(float* d, const uint32_t* a,
                                         const uint32_t* b) {
    asm volatile(
        "mma.sync.aligned.m16n8k16.row.col.f32.bf16.bf16.f32 "
        "{%0,%1,%2,%3}, {%4,%5,%6,%7}, {%8,%9}, {%0,%1,%2,%3};"
        : "+f"(d[0]), "+f"(d[1]), "+f"(d[2]), "+f"(d[3])
        : "r"(a[0]), "r"(a[1]), "r"(a[2]), "r"(a[3]), "r"(b[0]), "r"(b[1]));
}

// swizzled byte offset: 128B rows, 8 chunks of 16B, 8-way XOR
__device__ __forceinline__ uint32_t swoff(int r, int c) {
    return (uint32_t)(r * 128 + ((c ^ (r & 7)) << 4));
}

// ---------------- focal feature (fast intrinsics) ----------------
__device__ __forceinline__ float focal_feat(float x) {
    float p = 1.f / (1.f + __expf(-x));
    float q = 1.f - p;
    float neg = 0.75f * p * p * (-__logf(q + 1e-8f));
    float pos = 0.25f * q * q * (-__logf(p + 1e-8f));
    return pos - neg;
}

// ---------------- kernel 1: fused prep (features + targets) ----------------
__global__ void prep_kernel(const float* __restrict__ logits,
                            const float* __restrict__ label_maps,
                            const float* __restrict__ boxes,
                            const int*   __restrict__ class_labels) {
    int bid = blockIdx.x;
    int tid = threadIdx.x;
    if (bid < FEAT_BLOCKS) {
        int base = (bid * 256 + tid) * 8;
        float4 x0 = *(const float4*)(logits + base);
        float4 x1 = *(const float4*)(logits + base + 4);
        float f[8] = { x0.x, x0.y, x0.z, x0.w, x1.x, x1.y, x1.z, x1.w };
        __align__(16) __nv_bfloat16 ov[8];
        #pragma unroll
        for (int i = 0; i < 8; i++) ov[i] = __float2bfloat16(focal_feat(f[i]));
        *(uint4*)(g_A + base) = *(const uint4*)ov;
    } else {
        int j = bid - FEAT_BLOCKS;          // 0..639
        int b = j / Tt;
        int cls = class_labels[j];
        const float* row = label_maps + ((size_t)b * Ll + cls) * Cc;
        float2 v = *(const float2*)(row + tid * 2);
        float s = v.x + v.y;
        #pragma unroll
        for (int o = 16; o; o >>= 1) s += __shfl_xor_sync(0xffffffffu, s, o);
        __shared__ float red[8];
        if ((tid & 31) == 0) red[tid >> 5] = s;
        __syncthreads();
        float inv = 1.f / (red[0] + red[1] + red[2] + red[3] +
                           red[4] + red[5] + red[6] + red[7]);
        __nv_bfloat16 h0 = __float2bfloat16(v.x * inv);
        __nv_bfloat16 h1 = __float2bfloat16(v.y * inv);
        *(__nv_bfloat162*)(g_B + (size_t)j * Cc + tid * 2) =
            __nv_bfloat162(h0, h1);
        if (tid == 0) {
            float cx = boxes[j * 4 + 0], cy = boxes[j * 4 + 1];
            float w  = boxes[j * 4 + 2], h  = boxes[j * 4 + 3];
            float* o = g_tbox + j * 8;
            o[0] = cx; o[1] = cy; o[2] = w; o[3] = h;
            o[4] = cx - 0.5f * w; o[5] = cy - 0.5f * h;
            o[6] = cx + 0.5f * w; o[7] = cy + 0.5f * h;
        }
    }
}

// ---------------- kernel 2: mma.sync GEMM + fused cost epilogue ----------------
extern __shared__ char dynsmem[];

__global__ __launch_bounds__(256) void cost_kernel(
    const float* __restrict__ pred_boxes,
    float* __restrict__ outp) {

    const int tid = threadIdx.x;
    const int wid = tid >> 5;
    const int lane = tid & 31;
    const int wm = wid & 3;          // 4 warps in M (64 rows each)
    const int wn = wid >> 2;         // 2 warps in N (64 cols each)
    const int m0 = blockIdx.y * BM;
    const int n0 = blockIdx.x * BN;

    uint32_t smem = cvta_s(dynsmem);

    // per-thread ldmatrix in-stage offsets (4 k16-steps per BK=64 chunk)
    uint32_t aoff[4][4], boff[4][4];
    {
        int ar = wm * 64 + (lane & 15);
        int ac = lane >> 4;                       // 0..1
        #pragma unroll
        for (int mt = 0; mt < 4; mt++)
            #pragma unroll
            for (int ks = 0; ks < 4; ks++)
                aoff[mt][ks] = swoff(ar + mt * 16, ks * 2 + ac);
        int br = wn * 64 + ((lane >> 4) << 3) + (lane & 7);
        int bc = (lane >> 3) & 1;
        #pragma unroll
        for (int bp = 0; bp < 4; bp++)
            #pragma unroll
            for (int ks = 0; ks < 4; ks++)
                boff[bp][ks] = (uint32_t)A_BYTES + swoff(br + bp * 16, ks * 2 + bc);
    }

    // cp.async chunk loader: A 256x64 bf16, B 128x64 bf16, swizzled 16B granules
    auto issue = [&](int ch) {
        uint32_t st = smem + (ch % STAGES) * STAGE_BYTES;
        const __nv_bfloat16* Ag = g_A + (size_t)m0 * Cc + ch * BK;
        const __nv_bfloat16* Bg = g_B + (size_t)n0 * Cc + ch * BK;
        #pragma unroll
        for (int i = 0; i < 8; i++) {
            int idx = tid + i * 256;              // 0..2047
            int r = idx >> 3, c = idx & 7;
            CP16(st + swoff(r, c), Ag + (size_t)r * Cc + c * 8);
        }
        #pragma unroll
        for (int i = 0; i < 4; i++) {
            int idx = tid + i * 256;              // 0..1023
            int r = idx >> 3, c = idx & 7;
            CP16(st + A_BYTES + swoff(r, c), Bg + (size_t)r * Cc + c * 8);
        }
        CPCOMMIT();
    };

    float acc[4][8][4];
    #pragma unroll
    for (int i = 0; i < 4; i++)
        #pragma unroll
        for (int j = 0; j < 8; j++)
            #pragma unroll
            for (int e = 0; e < 4; e++) acc[i][j][e] = 0.f;

    issue(0); issue(1);

    for (int ch = 0; ch < NCH; ch++) {
        if (ch < NCH - 1) CPWAIT(1); else CPWAIT(0);
        __syncthreads();
        if (ch + 2 < NCH) issue(ch + 2);

        uint32_t st = smem + (ch % STAGES) * STAGE_BYTES;
        #pragma unroll
        for (int ks = 0; ks < 4; ks++) {
            uint32_t a[4][4], b[8][2];
            #pragma unroll
            for (int mt = 0; mt < 4; mt++)
                ldsm4(a[mt][0], a[mt][1], a[mt][2], a[mt][3], st + aoff[mt][ks]);
            #pragma unroll
            for (int bp = 0; bp < 4; bp++)
                ldsm4(b[2 * bp][0], b[2 * bp][1], b[2 * bp + 1][0], b[2 * bp + 1][1],
                      st + boff[bp][ks]);
            #pragma unroll
            for (int mt = 0; mt < 4; mt++)
                #pragma unroll
                for (int nt = 0; nt < 8; nt++)
                    mma_bf16(acc[mt][nt], a[mt], b[nt]);
        }
    }

    // ---------------- fused epilogue (register-resident) ----------------
    const int rbase = m0 + wm * 64 + (lane >> 2);
    const int cbase = n0 + wn * 64 + ((lane & 3) << 1);

    #pragma unroll
    for (int nt = 0; nt < 8; nt++) {
        int n = cbase + nt * 8;
        float4 tc0 = *(const float4*)(g_tbox + n * 8);
        float4 tk0 = *(const float4*)(g_tbox + n * 8 + 4);
        float4 tc1 = *(const float4*)(g_tbox + (n + 1) * 8);
        float4 tk1 = *(const float4*)(g_tbox + (n + 1) * 8 + 4);
        float ta0 = (tk0.z - tk0.x) * (tk0.w - tk0.y);
        float ta1 = (tk1.z - tk1.x) * (tk1.w - tk1.y);

        #pragma unroll
        for (int mt = 0; mt < 4; mt++) {
            #pragma unroll
            for (int half = 0; half < 2; half++) {
                int m = rbase + mt * 16 + half * 8;
                if (m >= BQn) continue;
                float4 qb = *(const float4*)(pred_boxes + (size_t)m * 4);
                float qx0 = qb.x - 0.5f * qb.z, qy0 = qb.y - 0.5f * qb.w;
                float qx1 = qb.x + 0.5f * qb.z, qy1 = qb.y + 0.5f * qb.w;
                float qarea = qb.z * qb.w;

                float r2[2];
                #pragma unroll
                for (int u = 0; u < 2; u++) {
                    float4 tc = u ? tc1 : tc0;
                    float4 tk = u ? tk1 : tk0;
                    float tarea = u ? ta1 : ta0;
                    float l1 = fabsf(qb.x - tc.x) + fabsf(qb.y - tc.y) +
                               fabsf(qb.z - tc.z) + fabsf(qb.w - tc.w);
                    float ltx = fmaxf(qx0, tk.x), lty = fmaxf(qy0, tk.y);
                    float rbx = fminf(qx1, tk.z), rby = fminf(qy1, tk.w);
                    float iw = fmaxf(rbx - ltx, 0.f), ih = fmaxf(rby - lty, 0.f);
                    float inter = iw * ih;
                    float uni = qarea + tarea - inter;
                    float iou = __fdividef(inter, uni);
                    float ex0 = fminf(qx0, tk.x), ey0 = fminf(qy0, tk.y);
                    float ex1 = fmaxf(qx1, tk.z), ey1 = fmaxf(qy1, tk.w);
                    float areaE = fmaxf(ex1 - ex0, 0.f) * fmaxf(ey1 - ey0, 0.f);
                    float giou = iou - __fdividef(areaE - uni, areaE);
                    float cls = acc[mt][nt][half * 2 + u];
                    r2[u] = 5.0f * l1 + 2.0f * cls - 2.0f * giou;
                }
                *(float2*)(outp + (size_t)m * BTn + n) = make_float2(r2[0], r2[1]);
            }
        }
    }
}

// ---------------- launcher ----------------
extern "C" void kernel_launch(void* const* d_in, const int* in_sizes, int n_in,
                              void* d_out, int out_size) {
    const float* logits       = (const float*)d_in[0];
    const float* pred_boxes   = (const float*)d_in[1];
    const float* label_maps   = (const float*)d_in[2];
    const float* boxes        = (const float*)d_in[3];
    const int*   class_labels = (const int*)d_in[4];
    float* out = (float*)d_out;

    cudaFuncSetAttribute(cost_kernel, cudaFuncAttributeMaxDynamicSharedMemorySize, DYNSMEM);

    prep_kernel<<<FEAT_BLOCKS + BTn, 256>>>(logits, label_maps, boxes, class_labels);
    cost_kernel<<<dim3(BTn / BN, MPAD / BM), 256, DYNSMEM>>>(pred_boxes, out);
}

// round 6
// speedup vs baseline: 1.0887x; 1.0887x over previous
#include <cuda_runtime.h>
#include <cuda_bf16.h>
#include <math.h>
#include <stdint.h>

// ---------------- problem constants ----------------
#define Tt   40
#define Ll   91
#define Cc   512
#define BQn  14400
#define BTn  640
#define MPAD 14464            // 113 * 128

// quantization scales (power of two: exact)
#define SA   16.0f
#define SB   512.0f
#define CLS_SCALE (2.0f / (SA * SB))   // 2 * (1/8192)

// ---------------- GEMM tiling (fp8: 1 byte/elt) ----------------
#define BM 128
#define BN 128
#define BKB 128               // K-bytes per chunk (128 fp8, 128B rows)
#define NCH 4                 // 512 / 128
#define STAGES 3
#define A_BYTES 16384         // 128 x 128B
#define STAGE_BYTES 32768     // A 16KB + B 16KB
#define DYNSMEM (STAGES * STAGE_BYTES)

#define FEAT_BLOCKS 3600      // BQn*Cc/8/256

// ---------------- scratch (zero-initialized device globals) ----------------
__device__ uint8_t g_A[(size_t)MPAD * Cc];   // fp8 e4m3 focal features * SA (pad rows zero)
__device__ uint8_t g_B[(size_t)BTn * Cc];    // fp8 e4m3 normalized lm * SB
__device__ float   g_tbox[BTn * 8];          // cx,cy,w,h,x0,y0,x1,y1

// ---------------- helpers ----------------
__device__ __forceinline__ uint32_t cvta_s(const void* p) {
    uint32_t a;
    asm("{ .reg .u64 t; cvta.to.shared.u64 t, %1; cvt.u32.u64 %0, t; }"
        : "=r"(a) : "l"(p));
    return a;
}

#define CP16(dst, src) asm volatile("cp.async.cg.shared.global [%0], [%1], 16;" :: "r"(dst), "l"(src))
#define CPCOMMIT()     asm volatile("cp.async.commit_group;")
#define CPWAIT(n)      asm volatile("cp.async.wait_group %0;" :: "n"(n))

__device__ __forceinline__ void ldsm4(uint32_t& r0, uint32_t& r1, uint32_t& r2,
                                      uint32_t& r3, uint32_t addr) {
    asm volatile("ldmatrix.sync.aligned.m8n8.x4.shared.b16 {%0,%1,%2,%3}, [%4];"
                 : "=r"(r0), "=r"(r1), "=r"(r2), "=r"(r3) : "r"(addr));
}

// fp8 e4m3 MMA: m16n8k32 — fragment bytes identical to bf16 m16n8k16
__device__ __forceinline__ void mma_fp8(float* d, const uint32_t* a,
                                        const uint32_t* b) {
    asm volatile(
        "mma.sync.aligned.m16n8k32.row.col.f32.e4m3.e4m3.f32 "
        "{%0,%1,%2,%3}, {%4,%5,%6,%7}, {%8,%9}, {%0,%1,%2,%3};"
        : "+f"(d[0]), "+f"(d[1]), "+f"(d[2]), "+f"(d[3])
        : "r"(a[0]), "r"(a[1]), "r"(a[2]), "r"(a[3]), "r"(b[0]), "r"(b[1]));
}

// pack two floats -> two e4m3 bytes (lo = first arg's convert goes to d<7:0>)
__device__ __forceinline__ uint16_t f2_to_e4m3x2(float lo, float hi) {
    uint16_t r;
    asm("cvt.rn.satfinite.e4m3x2.f32 %0, %1, %2;" : "=h"(r) : "f"(hi), "f"(lo));
    return r;
}

// swizzled byte offset: 128B rows, 8 chunks of 16B, 8-way XOR
__device__ __forceinline__ uint32_t swoff(int r, int c) {
    return (uint32_t)(r * 128 + ((c ^ (r & 7)) << 4));
}

// ---------------- focal feature (fast intrinsics) ----------------
__device__ __forceinline__ float focal_feat(float x) {
    float p = 1.f / (1.f + __expf(-x));
    float q = 1.f - p;
    float neg = 0.75f * p * p * (-__logf(q + 1e-8f));
    float pos = 0.25f * q * q * (-__logf(p + 1e-8f));
    return pos - neg;
}

// ---------------- kernel 1: fused prep (features + targets) ----------------
__global__ void prep_kernel(const float* __restrict__ logits,
                            const float* __restrict__ label_maps,
                            const float* __restrict__ boxes,
                            const int*   __restrict__ class_labels) {
    int bid = blockIdx.x;
    int tid = threadIdx.x;
    if (bid < FEAT_BLOCKS) {
        // one thread = 8 channels -> 8 fp8 bytes
        int base = (bid * 256 + tid) * 8;
        float4 x0 = *(const float4*)(logits + base);
        float4 x1 = *(const float4*)(logits + base + 4);
        float f[8] = { x0.x, x0.y, x0.z, x0.w, x1.x, x1.y, x1.z, x1.w };
        uint16_t w[4];
        #pragma unroll
        for (int i = 0; i < 4; i++)
            w[i] = f2_to_e4m3x2(focal_feat(f[2 * i]) * SA,
                                focal_feat(f[2 * i + 1]) * SA);
        uint2 pk;
        pk.x = (uint32_t)w[0] | ((uint32_t)w[1] << 16);
        pk.y = (uint32_t)w[2] | ((uint32_t)w[3] << 16);
        *(uint2*)(g_A + base) = pk;
    } else {
        int j = bid - FEAT_BLOCKS;          // 0..639
        int b = j / Tt;
        int cls = class_labels[j];
        const float* row = label_maps + ((size_t)b * Ll + cls) * Cc;
        float2 v = *(const float2*)(row + tid * 2);
        float s = v.x + v.y;
        #pragma unroll
        for (int o = 16; o; o >>= 1) s += __shfl_xor_sync(0xffffffffu, s, o);
        __shared__ float red[8];
        if ((tid & 31) == 0) red[tid >> 5] = s;
        __syncthreads();
        float inv = SB / (red[0] + red[1] + red[2] + red[3] +
                          red[4] + red[5] + red[6] + red[7]);
        *(uint16_t*)(g_B + (size_t)j * Cc + tid * 2) =
            f2_to_e4m3x2(v.x * inv, v.y * inv);
        if (tid == 0) {
            float cx = boxes[j * 4 + 0], cy = boxes[j * 4 + 1];
            float w  = boxes[j * 4 + 2], h  = boxes[j * 4 + 3];
            float* o = g_tbox + j * 8;
            o[0] = cx; o[1] = cy; o[2] = w; o[3] = h;
            o[4] = cx - 0.5f * w; o[5] = cy - 0.5f * h;
            o[6] = cx + 0.5f * w; o[7] = cy + 0.5f * h;
        }
    }
}

// ---------------- kernel 2: fp8 mma.sync GEMM + fused cost epilogue ----------------
extern __shared__ char dynsmem[];

__global__ __launch_bounds__(256, 2) void cost_kernel(
    const float* __restrict__ pred_boxes,
    float* __restrict__ outp) {

    const int tid = threadIdx.x;
    const int wid = tid >> 5;
    const int lane = tid & 31;
    const int wm = wid & 1;          // 2 warps in M
    const int wn = wid >> 1;         // 4 warps in N
    const int m0 = blockIdx.y * BM;
    const int n0 = blockIdx.x * BN;

    uint32_t smem = cvta_s(dynsmem);

    // per-thread ldmatrix offsets: 4 k32-steps per 128B chunk (each step = 32B = 2x16B)
    uint32_t aoff[4][4], boff[2][4];
    {
        int ar = wm * 64 + (lane & 15);
        int ac = lane >> 4;                       // 0..1
        #pragma unroll
        for (int mt = 0; mt < 4; mt++)
            #pragma unroll
            for (int ks = 0; ks < 4; ks++)
                aoff[mt][ks] = swoff(ar + mt * 16, ks * 2 + ac);
        int br = wn * 32 + ((lane >> 4) << 3) + (lane & 7);
        int bc = (lane >> 3) & 1;
        #pragma unroll
        for (int bp = 0; bp < 2; bp++)
            #pragma unroll
            for (int ks = 0; ks < 4; ks++)
                boff[bp][ks] = (uint32_t)A_BYTES + swoff(br + bp * 16, ks * 2 + bc);
    }

    // cp.async chunk loader: A 128x128B, B 128x128B, 16B granules, swizzled
    auto issue = [&](int ch) {
        uint32_t st = smem + (ch % STAGES) * STAGE_BYTES;
        const uint8_t* Ag = g_A + (size_t)m0 * Cc + ch * BKB;
        const uint8_t* Bg = g_B + (size_t)n0 * Cc + ch * BKB;
        #pragma unroll
        for (int i = 0; i < 4; i++) {
            int idx = tid + i * 256;              // 0..1023
            int r = idx >> 3, c = idx & 7;
            CP16(st + swoff(r, c), Ag + (size_t)r * Cc + c * 16);
        }
        #pragma unroll
        for (int i = 0; i < 4; i++) {
            int idx = tid + i * 256;
            int r = idx >> 3, c = idx & 7;
            CP16(st + A_BYTES + swoff(r, c), Bg + (size_t)r * Cc + c * 16);
        }
        CPCOMMIT();
    };

    float acc[4][4][4];
    #pragma unroll
    for (int i = 0; i < 4; i++)
        #pragma unroll
        for (int j = 0; j < 4; j++)
            #pragma unroll
            for (int e = 0; e < 4; e++) acc[i][j][e] = 0.f;

    issue(0); issue(1);

    for (int ch = 0; ch < NCH; ch++) {
        if (ch < NCH - 1) CPWAIT(1); else CPWAIT(0);
        __syncthreads();
        if (ch + 2 < NCH) issue(ch + 2);

        uint32_t st = smem + (ch % STAGES) * STAGE_BYTES;
        #pragma unroll
        for (int ks = 0; ks < 4; ks++) {
            uint32_t a[4][4], b[4][2];
            #pragma unroll
            for (int mt = 0; mt < 4; mt++)
                ldsm4(a[mt][0], a[mt][1], a[mt][2], a[mt][3], st + aoff[mt][ks]);
            #pragma unroll
            for (int bp = 0; bp < 2; bp++)
                ldsm4(b[2 * bp][0], b[2 * bp][1], b[2 * bp + 1][0], b[2 * bp + 1][1],
                      st + boff[bp][ks]);
            #pragma unroll
            for (int mt = 0; mt < 4; mt++)
                #pragma unroll
                for (int nt = 0; nt < 4; nt++)
                    mma_fp8(acc[mt][nt], a[mt], b[nt]);
        }
    }

    // ---------------- fused epilogue (register-resident) ----------------
    const int rbase = m0 + wm * 64 + (lane >> 2);
    const int cbase = n0 + wn * 32 + ((lane & 3) << 1);

    #pragma unroll
    for (int nt = 0; nt < 4; nt++) {
        int n = cbase + nt * 8;
        float4 tc0 = *(const float4*)(g_tbox + n * 8);
        float4 tk0 = *(const float4*)(g_tbox + n * 8 + 4);
        float4 tc1 = *(const float4*)(g_tbox + (n + 1) * 8);
        float4 tk1 = *(const float4*)(g_tbox + (n + 1) * 8 + 4);
        float ta0 = (tk0.z - tk0.x) * (tk0.w - tk0.y);
        float ta1 = (tk1.z - tk1.x) * (tk1.w - tk1.y);

        #pragma unroll
        for (int mt = 0; mt < 4; mt++) {
            #pragma unroll
            for (int half = 0; half < 2; half++) {
                int m = rbase + mt * 16 + half * 8;
                if (m >= BQn) continue;
                float4 qb = *(const float4*)(pred_boxes + (size_t)m * 4);
                float qx0 = qb.x - 0.5f * qb.z, qy0 = qb.y - 0.5f * qb.w;
                float qx1 = qb.x + 0.5f * qb.z, qy1 = qb.y + 0.5f * qb.w;
                float qarea = qb.z * qb.w;

                float r2[2];
                #pragma unroll
                for (int u = 0; u < 2; u++) {
                    float4 tc = u ? tc1 : tc0;
                    float4 tk = u ? tk1 : tk0;
                    float tarea = u ? ta1 : ta0;
                    float l1 = fabsf(qb.x - tc.x) + fabsf(qb.y - tc.y) +
                               fabsf(qb.z - tc.z) + fabsf(qb.w - tc.w);
                    float ltx = fmaxf(qx0, tk.x), lty = fmaxf(qy0, tk.y);
                    float rbx = fminf(qx1, tk.z), rby = fminf(qy1, tk.w);
                    float iw = fmaxf(rbx - ltx, 0.f), ih = fmaxf(rby - lty, 0.f);
                    float inter = iw * ih;
                    float uni = qarea + tarea - inter;
                    float iou = __fdividef(inter, uni);
                    float ex0 = fminf(qx0, tk.x), ey0 = fminf(qy0, tk.y);
                    float ex1 = fmaxf(qx1, tk.z), ey1 = fmaxf(qy1, tk.w);
                    float areaE = fmaxf(ex1 - ex0, 0.f) * fmaxf(ey1 - ey0, 0.f);
                    float giou = iou - __fdividef(areaE - uni, areaE);
                    float cls = acc[mt][nt][half * 2 + u];
                    r2[u] = 5.0f * l1 + CLS_SCALE * cls - 2.0f * giou;
                }
                *(float2*)(outp + (size_t)m * BTn + n) = make_float2(r2[0], r2[1]);
            }
        }
    }
}

// ---------------- launcher ----------------
extern "C" void kernel_launch(void* const* d_in, const int* in_sizes, int n_in,
                              void* d_out, int out_size) {
    const float* logits       = (const float*)d_in[0];
    const float* pred_boxes   = (const float*)d_in[1];
    const float* label_maps   = (const float*)d_in[2];
    const float* boxes        = (const float*)d_in[3];
    const int*   class_labels = (const int*)d_in[4];
    float* out = (float*)d_out;

    cudaFuncSetAttribute(cost_kernel, cudaFuncAttributeMaxDynamicSharedMemorySize, DYNSMEM);

    prep_kernel<<<FEAT_BLOCKS + BTn, 256>>>(logits, label_maps, boxes, class_labels);
    cost_kernel<<<dim3(BTn / BN, MPAD / BM), 256, DYNSMEM>>>(pred_boxes, out);
}

// round 8
// speedup vs baseline: 1.1697x; 1.0744x over previous
#include <cuda_runtime.h>
#include <cuda_bf16.h>
#include <math.h>
#include <stdint.h>

// ---------------- problem constants ----------------
#define Tt   40
#define Ll   91
#define Cc   512
#define BQn  14400
#define BTn  640
#define MPAD 14464            // 113 * 128

// quantization scales (power of two: exact)
#define SA   16.0f
#define SB   512.0f
#define CLS_SCALE (2.0f / (SA * SB))

// ---------------- GEMM tiling (fp8: 1 byte/elt) ----------------
#define BM 128
#define BN 64
#define BKB 128               // K-bytes per chunk (128 fp8, 128B rows)
#define NCH 4                 // 512 / 128
#define STAGES 3
#define A_BYTES 16384         // 128 x 128B
#define B_BYTES 8192          // 64 x 128B
#define STAGE_BYTES (A_BYTES + B_BYTES)   // 24KB
#define DYNSMEM (STAGES * STAGE_BYTES)    // 72KB

#define FEAT_BLOCKS 3600      // BQn*Cc/8/256

// ---------------- scratch (zero-initialized device globals) ----------------
__device__ uint8_t g_A[(size_t)MPAD * Cc];   // fp8 e4m3 focal features * SA (pad rows zero)
__device__ uint8_t g_B[(size_t)BTn * Cc];    // fp8 e4m3 normalized lm * SB
__device__ float   g_tbox[BTn * 8];          // cx,cy,w,h,x0,y0,x1,y1

// ---------------- helpers ----------------
__device__ __forceinline__ uint32_t cvta_s(const void* p) {
    uint32_t a;
    asm("{ .reg .u64 t; cvta.to.shared.u64 t, %1; cvt.u32.u64 %0, t; }"
        : "=r"(a) : "l"(p));
    return a;
}

#define CP16(dst, src) asm volatile("cp.async.cg.shared.global [%0], [%1], 16;" :: "r"(dst), "l"(src))
#define CPCOMMIT()     asm volatile("cp.async.commit_group;")
#define CPWAIT(n)      asm volatile("cp.async.wait_group %0;" :: "n"(n))

__device__ __forceinline__ void ldsm4(uint32_t& r0, uint32_t& r1, uint32_t& r2,
                                      uint32_t& r3, uint32_t addr) {
    asm volatile("ldmatrix.sync.aligned.m8n8.x4.shared.b16 {%0,%1,%2,%3}, [%4];"
                 : "=r"(r0), "=r"(r1), "=r"(r2), "=r"(r3) : "r"(addr));
}

__device__ __forceinline__ void mma_fp8(float* d, const uint32_t* a,
                                        const uint32_t* b) {
    asm volatile(
        "mma.sync.aligned.m16n8k32.row.col.f32.e4m3.e4m3.f32 "
        "{%0,%1,%2,%3}, {%4,%5,%6,%7}, {%8,%9}, {%0,%1,%2,%3};"
        : "+f"(d[0]), "+f"(d[1]), "+f"(d[2]), "+f"(d[3])
        : "r"(a[0]), "r"(a[1]), "r"(a[2]), "r"(a[3]), "r"(b[0]), "r"(b[1]));
}

__device__ __forceinline__ uint16_t f2_to_e4m3x2(float lo, float hi) {
    uint16_t r;
    asm("cvt.rn.satfinite.e4m3x2.f32 %0, %1, %2;" : "=h"(r) : "f"(hi), "f"(lo));
    return r;
}

// swizzled byte offset: 128B rows, 8 chunks of 16B, 8-way XOR
__device__ __forceinline__ uint32_t swoff(int r, int c) {
    return (uint32_t)(r * 128 + ((c ^ (r & 7)) << 4));
}

// ---------------- focal feature (fast intrinsics) ----------------
__device__ __forceinline__ float focal_feat(float x) {
    float p = 1.f / (1.f + __expf(-x));
    float q = 1.f - p;
    float neg = 0.75f * p * p * (-__logf(q + 1e-8f));
    float pos = 0.25f * q * q * (-__logf(p + 1e-8f));
    return pos - neg;
}

// ---------------- kernel 1: fused prep (features + targets) ----------------
__global__ void prep_kernel(const float* __restrict__ logits,
                            const float* __restrict__ label_maps,
                            const float* __restrict__ boxes,
                            const int*   __restrict__ class_labels) {
    int bid = blockIdx.x;
    int tid = threadIdx.x;
    if (bid < FEAT_BLOCKS) {
        int base = (bid * 256 + tid) * 8;
        float4 x0 = *(const float4*)(logits + base);
        float4 x1 = *(const float4*)(logits + base + 4);
        float f[8] = { x0.x, x0.y, x0.z, x0.w, x1.x, x1.y, x1.z, x1.w };
        uint16_t w[4];
        #pragma unroll
        for (int i = 0; i < 4; i++)
            w[i] = f2_to_e4m3x2(focal_feat(f[2 * i]) * SA,
                                focal_feat(f[2 * i + 1]) * SA);
        uint2 pk;
        pk.x = (uint32_t)w[0] | ((uint32_t)w[1] << 16);
        pk.y = (uint32_t)w[2] | ((uint32_t)w[3] << 16);
        *(uint2*)(g_A + base) = pk;
    } else {
        int j = bid - FEAT_BLOCKS;          // 0..639
        int b = j / Tt;
        int cls = class_labels[j];
        const float* row = label_maps + ((size_t)b * Ll + cls) * Cc;
        float2 v = *(const float2*)(row + tid * 2);
        float s = v.x + v.y;
        #pragma unroll
        for (int o = 16; o; o >>= 1) s += __shfl_xor_sync(0xffffffffu, s, o);
        __shared__ float red[8];
        if ((tid & 31) == 0) red[tid >> 5] = s;
        __syncthreads();
        float inv = SB / (red[0] + red[1] + red[2] + red[3] +
                          red[4] + red[5] + red[6] + red[7]);
        *(uint16_t*)(g_B + (size_t)j * Cc + tid * 2) =
            f2_to_e4m3x2(v.x * inv, v.y * inv);
        if (tid == 0) {
            float cx = boxes[j * 4 + 0], cy = boxes[j * 4 + 1];
            float w  = boxes[j * 4 + 2], h  = boxes[j * 4 + 3];
            float* o = g_tbox + j * 8;
            o[0] = cx; o[1] = cy; o[2] = w; o[3] = h;
            o[4] = cx - 0.5f * w; o[5] = cy - 0.5f * h;
            o[6] = cx + 0.5f * w; o[7] = cy + 0.5f * h;
        }
    }
}

// ---------------- kernel 2: fp8 mma.sync GEMM + fused cost epilogue ----------------
extern __shared__ char dynsmem[];

__global__ __launch_bounds__(256, 3) void cost_kernel(
    const float* __restrict__ pred_boxes,
    float* __restrict__ outp) {

    const int tid = threadIdx.x;
    const int wid = tid >> 5;
    const int lane = tid & 31;
    const int wm = wid & 3;          // 4 warps in M (32 rows each)
    const int wn = wid >> 2;         // 2 warps in N (32 cols each)
    const int m0 = blockIdx.y * BM;
    const int n0 = blockIdx.x * BN;

    uint32_t smem = cvta_s(dynsmem);
    __shared__ float s_tbox[BN * 8];     // target boxes for this N-tile (2KB)

    // stage target boxes once
    #pragma unroll
    for (int i = tid; i < BN * 2; i += 256)
        ((float4*)s_tbox)[i] = *(const float4*)(g_tbox + (size_t)n0 * 8 + i * 4);

    // per-thread ldmatrix offsets: 4 k32-steps per 128B chunk
    uint32_t aoff[2][4], boff[2][4];
    {
        int ar = wm * 32 + (lane & 15);
        int ac = lane >> 4;                       // 0..1
        #pragma unroll
        for (int mt = 0; mt < 2; mt++)
            #pragma unroll
            for (int ks = 0; ks < 4; ks++)
                aoff[mt][ks] = swoff(ar + mt * 16, ks * 2 + ac);
        int br = wn * 32 + ((lane >> 4) << 3) + (lane & 7);
        int bc = (lane >> 3) & 1;
        #pragma unroll
        for (int bp = 0; bp < 2; bp++)
            #pragma unroll
            for (int ks = 0; ks < 4; ks++)
                boff[bp][ks] = (uint32_t)A_BYTES + swoff(br + bp * 16, ks * 2 + bc);
    }

    // cp.async chunk loader: A 128x128B, B 64x128B, 16B granules, swizzled
    auto issue = [&](int ch) {
        uint32_t st = smem + (ch % STAGES) * STAGE_BYTES;
        const uint8_t* Ag = g_A + (size_t)m0 * Cc + ch * BKB;
        const uint8_t* Bg = g_B + (size_t)n0 * Cc + ch * BKB;
        #pragma unroll
        for (int i = 0; i < 4; i++) {
            int idx = tid + i * 256;              // 0..1023
            int r = idx >> 3, c = idx & 7;
            CP16(st + swoff(r, c), Ag + (size_t)r * Cc + c * 16);
        }
        #pragma unroll
        for (int i = 0; i < 2; i++) {
            int idx = tid + i * 256;              // 0..511
            int r = idx >> 3, c = idx & 7;
            CP16(st + A_BYTES + swoff(r, c), Bg + (size_t)r * Cc + c * 16);
        }
        CPCOMMIT();
    };

    float acc[2][4][4];
    #pragma unroll
    for (int i = 0; i < 2; i++)
        #pragma unroll
        for (int j = 0; j < 4; j++)
            #pragma unroll
            for (int e = 0; e < 4; e++) acc[i][j][e] = 0.f;

    issue(0); issue(1);

    for (int ch = 0; ch < NCH; ch++) {
        if (ch < NCH - 1) CPWAIT(1); else CPWAIT(0);
        __syncthreads();
        if (ch + 2 < NCH) issue(ch + 2);

        uint32_t st = smem + (ch % STAGES) * STAGE_BYTES;
        #pragma unroll
        for (int ks = 0; ks < 4; ks++) {
            uint32_t a[2][4], b[4][2];
            #pragma unroll
            for (int mt = 0; mt < 2; mt++)
                ldsm4(a[mt][0], a[mt][1], a[mt][2], a[mt][3], st + aoff[mt][ks]);
            #pragma unroll
            for (int bp = 0; bp < 2; bp++)
                ldsm4(b[2 * bp][0], b[2 * bp][1], b[2 * bp + 1][0], b[2 * bp + 1][1],
                      st + boff[bp][ks]);
            #pragma unroll
            for (int mt = 0; mt < 2; mt++)
                #pragma unroll
                for (int nt = 0; nt < 4; nt++)
                    mma_fp8(acc[mt][nt], a[mt], b[nt]);
        }
    }

    // ---------------- fused epilogue ----------------
    const int rbase = m0 + wm * 32 + (lane >> 2);
    const int cbase = wn * 32 + ((lane & 3) << 1);   // local col within tile

    // hoist the 4 pred_boxes rows this thread owns
    float4 qb[2][2];
    #pragma unroll
    for (int mt = 0; mt < 2; mt++)
        #pragma unroll
        for (int half = 0; half < 2; half++) {
            int m = rbase + mt * 16 + half * 8;
            qb[mt][half] = (m < BQn) ? *(const float4*)(pred_boxes + (size_t)m * 4)
                                     : make_float4(0.f, 0.f, 0.f, 0.f);
        }

    #pragma unroll
    for (int nt = 0; nt < 4; nt++) {
        int nl = cbase + nt * 8;                    // local target col (pair base)
        float4 tc0 = *(const float4*)(s_tbox + nl * 8);
        float4 tk0 = *(const float4*)(s_tbox + nl * 8 + 4);
        float4 tc1 = *(const float4*)(s_tbox + (nl + 1) * 8);
        float4 tk1 = *(const float4*)(s_tbox + (nl + 1) * 8 + 4);
        float ta0 = (tk0.z - tk0.x) * (tk0.w - tk0.y);
        float ta1 = (tk1.z - tk1.x) * (tk1.w - tk1.y);

        #pragma unroll
        for (int mt = 0; mt < 2; mt++) {
            #pragma unroll
            for (int half = 0; half < 2; half++) {
                int m = rbase + mt * 16 + half * 8;
                if (m >= BQn) continue;
                float4 q = qb[mt][half];
                float qx0 = q.x - 0.5f * q.z, qy0 = q.y - 0.5f * q.w;
                float qx1 = q.x + 0.5f * q.z, qy1 = q.y + 0.5f * q.w;
                float qarea = q.z * q.w;

                float r2[2];
                #pragma unroll
                for (int u = 0; u < 2; u++) {
                    float4 tc = u ? tc1 : tc0;
                    float4 tk = u ? tk1 : tk0;
                    float tarea = u ? ta1 : ta0;
                    float l1 = fabsf(q.x - tc.x) + fabsf(q.y - tc.y) +
                               fabsf(q.z - tc.z) + fabsf(q.w - tc.w);
                    float ltx = fmaxf(qx0, tk.x), lty = fmaxf(qy0, tk.y);
                    float rbx = fminf(qx1, tk.z), rby = fminf(qy1, tk.w);
                    float iw = fmaxf(rbx - ltx, 0.f), ih = fmaxf(rby - lty, 0.f);
                    float inter = iw * ih;
                    float uni = qarea + tarea - inter;
                    float iou = __fdividef(inter, uni);
                    float ex0 = fminf(qx0, tk.x), ey0 = fminf(qy0, tk.y);
                    float ex1 = fmaxf(qx1, tk.z), ey1 = fmaxf(qy1, tk.w);
                    float areaE = fmaxf(ex1 - ex0, 0.f) * fmaxf(ey1 - ey0, 0.f);
                    float giou = iou - __fdividef(areaE - uni, areaE);
                    float cls = acc[mt][nt][half * 2 + u];
                    r2[u] = 5.0f * l1 + CLS_SCALE * cls - 2.0f * giou;
                }
                *(float2*)(outp + (size_t)m * BTn + n0 + nl) = make_float2(r2[0], r2[1]);
            }
        }
    }
}

// ---------------- launcher ----------------
extern "C" void kernel_launch(void* const* d_in, const int* in_sizes, int n_in,
                              void* d_out, int out_size) {
    const float* logits       = (const float*)d_in[0];
    const float* pred_boxes   = (const float*)d_in[1];
    const float* label_maps   = (const float*)d_in[2];
    const float* boxes        = (const float*)d_in[3];
    const int*   class_labels = (const int*)d_in[4];
    float* out = (float*)d_out;

    cudaFuncSetAttribute(cost_kernel, cudaFuncAttributeMaxDynamicSharedMemorySize, DYNSMEM);

    prep_kernel<<<FEAT_BLOCKS + BTn, 256>>>(logits, label_maps, boxes, class_labels);
    cost_kernel<<<dim3(BTn / BN, MPAD / BM), 256, DYNSMEM>>>(pred_boxes, out);
}

// round 9
// speedup vs baseline: 1.2973x; 1.1091x over previous
#include <cuda_runtime.h>
#include <cuda_bf16.h>
#include <math.h>
#include <stdint.h>

// ---------------- problem constants ----------------
#define Tt   40
#define Ll   91
#define Cc   512
#define BQn  14400
#define BTn  640
#define MPAD 14464            // 113 * 128

// quantization scales (power of two: exact)
#define SA   16.0f
#define SB   512.0f
#define CLS_SCALE (2.0f / (SA * SB))

// ---------------- GEMM tiling (fp8: 1 byte/elt) ----------------
#define BM 128
#define BN 64
#define BKB 128               // K-bytes per chunk
#define NCH 4                 // 512 / 128
#define B_ALL_BYTES 32768     // 64 rows x 512B, as 4 chunks of 8KB
#define A_OFF 32768           // A pair buffers start here
#define A_PAIR_BYTES 8192     // 2 stages x 32 rows x 128B
#define DYNSMEM 65536         // 32KB B + 32KB A

#define FEAT_BLOCKS 3600      // BQn*Cc/8/256

// ---------------- scratch (zero-initialized device globals) ----------------
__device__ uint8_t g_A[(size_t)MPAD * Cc];   // fp8 e4m3 focal features * SA (pad rows zero)
__device__ uint8_t g_B[(size_t)BTn * Cc];    // fp8 e4m3 normalized lm * SB
__device__ float   g_tbox[BTn * 8];          // cx,cy,w,h,x0,y0,x1,y1

// ---------------- helpers ----------------
__device__ __forceinline__ uint32_t cvta_s(const void* p) {
    uint32_t a;
    asm("{ .reg .u64 t; cvta.to.shared.u64 t, %1; cvt.u32.u64 %0, t; }"
        : "=r"(a) : "l"(p));
    return a;
}

#define CP16(dst, src) asm volatile("cp.async.cg.shared.global [%0], [%1], 16;" :: "r"(dst), "l"(src))
#define CPCOMMIT()     asm volatile("cp.async.commit_group;")
#define CPWAIT(n)      asm volatile("cp.async.wait_group %0;" :: "n"(n))
#define PAIR_BAR(id)   asm volatile("bar.sync %0, 64;" :: "r"(id) : "memory")

__device__ __forceinline__ void ldsm4(uint32_t& r0, uint32_t& r1, uint32_t& r2,
                                      uint32_t& r3, uint32_t addr) {
    asm volatile("ldmatrix.sync.aligned.m8n8.x4.shared.b16 {%0,%1,%2,%3}, [%4];"
                 : "=r"(r0), "=r"(r1), "=r"(r2), "=r"(r3) : "r"(addr));
}

__device__ __forceinline__ void mma_fp8(float* d, const uint32_t* a,
                                        const uint32_t* b) {
    asm volatile(
        "mma.sync.aligned.m16n8k32.row.col.f32.e4m3.e4m3.f32 "
        "{%0,%1,%2,%3}, {%4,%5,%6,%7}, {%8,%9}, {%0,%1,%2,%3};"
        : "+f"(d[0]), "+f"(d[1]), "+f"(d[2]), "+f"(d[3])
        : "r"(a[0]), "r"(a[1]), "r"(a[2]), "r"(a[3]), "r"(b[0]), "r"(b[1]));
}

__device__ __forceinline__ uint16_t f2_to_e4m3x2(float lo, float hi) {
    uint16_t r;
    asm("cvt.rn.satfinite.e4m3x2.f32 %0, %1, %2;" : "=h"(r) : "f"(hi), "f"(lo));
    return r;
}

// swizzled byte offset: 128B rows, 8 chunks of 16B, 8-way XOR
__device__ __forceinline__ uint32_t swoff(int r, int c) {
    return (uint32_t)(r * 128 + ((c ^ (r & 7)) << 4));
}

// ---------------- focal feature: 3-MUFU softplus form ----------------
// -log(sigmoid(x)) = log1p(e^-x) = t ;  -log(1-sigmoid(x)) = x + t
__device__ __forceinline__ float focal_feat(float x) {
    float e = __expf(-x);
    float t = __logf(1.f + e);
    float p = __fdividef(1.f, 1.f + e);
    float q = 1.f - p;
    return 0.25f * q * q * t - 0.75f * p * p * (x + t);
}

// ---------------- kernel 1: fused prep (features + targets) ----------------
__global__ void prep_kernel(const float* __restrict__ logits,
                            const float* __restrict__ label_maps,
                            const float* __restrict__ boxes,
                            const int*   __restrict__ class_labels) {
    int bid = blockIdx.x;
    int tid = threadIdx.x;
    if (bid < FEAT_BLOCKS) {
        int base = (bid * 256 + tid) * 8;
        float4 x0 = *(const float4*)(logits + base);
        float4 x1 = *(const float4*)(logits + base + 4);
        float f[8] = { x0.x, x0.y, x0.z, x0.w, x1.x, x1.y, x1.z, x1.w };
        uint16_t w[4];
        #pragma unroll
        for (int i = 0; i < 4; i++)
            w[i] = f2_to_e4m3x2(focal_feat(f[2 * i]) * SA,
                                focal_feat(f[2 * i + 1]) * SA);
        uint2 pk;
        pk.x = (uint32_t)w[0] | ((uint32_t)w[1] << 16);
        pk.y = (uint32_t)w[2] | ((uint32_t)w[3] << 16);
        *(uint2*)(g_A + base) = pk;
    } else {
        int j = bid - FEAT_BLOCKS;          // 0..639
        int b = j / Tt;
        int cls = class_labels[j];
        const float* row = label_maps + ((size_t)b * Ll + cls) * Cc;
        float2 v = *(const float2*)(row + tid * 2);
        float s = v.x + v.y;
        #pragma unroll
        for (int o = 16; o; o >>= 1) s += __shfl_xor_sync(0xffffffffu, s, o);
        __shared__ float red[8];
        if ((tid & 31) == 0) red[tid >> 5] = s;
        __syncthreads();
        float inv = SB / (red[0] + red[1] + red[2] + red[3] +
                          red[4] + red[5] + red[6] + red[7]);
        *(uint16_t*)(g_B + (size_t)j * Cc + tid * 2) =
            f2_to_e4m3x2(v.x * inv, v.y * inv);
        if (tid == 0) {
            float cx = boxes[j * 4 + 0], cy = boxes[j * 4 + 1];
            float w  = boxes[j * 4 + 2], h  = boxes[j * 4 + 3];
            float* o = g_tbox + j * 8;
            o[0] = cx; o[1] = cy; o[2] = w; o[3] = h;
            o[4] = cx - 0.5f * w; o[5] = cy - 0.5f * h;
            o[6] = cx + 0.5f * w; o[7] = cy + 0.5f * h;
        }
    }
}

// ---------------- kernel 2: fp8 GEMM, warp-pair pipelines, fused epilogue ----------------
extern __shared__ char dynsmem[];

__global__ __launch_bounds__(256, 3) void cost_kernel(
    const float* __restrict__ pred_boxes,
    float* __restrict__ outp) {

    const int tid = threadIdx.x;
    const int wid = tid >> 5;
    const int lane = tid & 31;
    const int pair = wid & 3;        // pair owns A rows [pair*32, pair*32+32)
    const int wn = wid >> 2;         // 0/1: B column half
    const int l64 = (wn << 5) | lane;     // 0..63 within pair
    const int m0 = blockIdx.y * BM;
    const int n0 = blockIdx.x * BN;

    uint32_t smem = cvta_s(dynsmem);
    const uint32_t a_base = smem + A_OFF + pair * A_PAIR_BYTES;
    __shared__ float s_tbox[BN * 8];     // target boxes for this N-tile (2KB)

    // stage target boxes
    #pragma unroll
    for (int i = tid; i < BN * 2; i += 256)
        ((float4*)s_tbox)[i] = *(const float4*)(g_tbox + (size_t)n0 * 8 + i * 4);

    // ---- prologue loads ----
    // B: whole 64x512 tile as 4 chunks of 64x128B (group 1, all threads)
    {
        #pragma unroll
        for (int i = 0; i < 8; i++) {
            int idx = tid + i * 256;          // 0..2047
            int ch = idx >> 9;
            int w9 = idx & 511;
            int r = w9 >> 3, c = w9 & 7;
            CP16(smem + ch * 8192 + swoff(r, c),
                 g_B + (size_t)(n0 + r) * Cc + ch * BKB + c * 16);
        }
        CPCOMMIT();
    }
    // A chunks 0,1 into pair-private double buffer (pair's 64 lanes)
    auto issueA = [&](int ch) {
        uint32_t st = a_base + (ch & 1) * 4096;
        const uint8_t* Ag = g_A + (size_t)(m0 + pair * 32) * Cc + ch * BKB;
        #pragma unroll
        for (int i = 0; i < 4; i++) {
            int idx = l64 + i * 64;           // 0..255
            int r = idx >> 3, c = idx & 7;
            CP16(st + swoff(r, c), Ag + (size_t)r * Cc + c * 16);
        }
        CPCOMMIT();
    };
    issueA(0); issueA(1);

    CPWAIT(2);             // B complete (per-thread oldest group)
    __syncthreads();       // B visible CTA-wide; only CTA-wide sync in kernel

    // per-thread ldmatrix offsets
    uint32_t aoff[2][4], boff[2][4];
    {
        int ar = lane & 15;                       // row within pair's 32
        int ac = lane >> 4;
        #pragma unroll
        for (int mt = 0; mt < 2; mt++)
            #pragma unroll
            for (int ks = 0; ks < 4; ks++)
                aoff[mt][ks] = swoff(ar + mt * 16, ks * 2 + ac);
        int br = wn * 32 + ((lane >> 4) << 3) + (lane & 7);
        int bc = (lane >> 3) & 1;
        #pragma unroll
        for (int bp = 0; bp < 2; bp++)
            #pragma unroll
            for (int ks = 0; ks < 4; ks++)
                boff[bp][ks] = swoff(br + bp * 16, ks * 2 + bc);
    }

    float acc[2][4][4];
    #pragma unroll
    for (int i = 0; i < 2; i++)
        #pragma unroll
        for (int j = 0; j < 4; j++)
            #pragma unroll
            for (int e = 0; e < 4; e++) acc[i][j][e] = 0.f;

    // ---- mainloop: pair-local pipeline, no CTA barriers ----
    #pragma unroll
    for (int ch = 0; ch < NCH; ch++) {
        if (ch < NCH - 1) CPWAIT(1); else CPWAIT(0);
        PAIR_BAR(pair + 1);                       // pair's A(ch) fully visible

        uint32_t ast = a_base + (ch & 1) * 4096;
        uint32_t bst = smem + ch * 8192;
        #pragma unroll
        for (int ks = 0; ks < 4; ks++) {
            uint32_t a[2][4], b[4][2];
            #pragma unroll
            for (int mt = 0; mt < 2; mt++)
                ldsm4(a[mt][0], a[mt][1], a[mt][2], a[mt][3], ast + aoff[mt][ks]);
            #pragma unroll
            for (int bp = 0; bp < 2; bp++)
                ldsm4(b[2 * bp][0], b[2 * bp][1], b[2 * bp + 1][0], b[2 * bp + 1][1],
                      bst + boff[bp][ks]);
            #pragma unroll
            for (int mt = 0; mt < 2; mt++)
                #pragma unroll
                for (int nt = 0; nt < 4; nt++)
                    mma_fp8(acc[mt][nt], a[mt], b[nt]);
        }

        if (ch + 2 < NCH) {
            PAIR_BAR(pair + 1);                   // both warps done reading stage
            issueA(ch + 2);
        }
    }

    // ---------------- fused epilogue ----------------
    const int rbase = m0 + pair * 32 + (lane >> 2);
    const int cbase = wn * 32 + ((lane & 3) << 1);

    float4 qb[2][2];
    #pragma unroll
    for (int mt = 0; mt < 2; mt++)
        #pragma unroll
        for (int half = 0; half < 2; half++) {
            int m = rbase + mt * 16 + half * 8;
            qb[mt][half] = (m < BQn) ? *(const float4*)(pred_boxes + (size_t)m * 4)
                                     : make_float4(0.f, 0.f, 0.f, 0.f);
        }

    #pragma unroll
    for (int nt = 0; nt < 4; nt++) {
        int nl = cbase + nt * 8;
        float4 tc0 = *(const float4*)(s_tbox + nl * 8);
        float4 tk0 = *(const float4*)(s_tbox + nl * 8 + 4);
        float4 tc1 = *(const float4*)(s_tbox + (nl + 1) * 8);
        float4 tk1 = *(const float4*)(s_tbox + (nl + 1) * 8 + 4);
        float ta0 = (tk0.z - tk0.x) * (tk0.w - tk0.y);
        float ta1 = (tk1.z - tk1.x) * (tk1.w - tk1.y);

        #pragma unroll
        for (int mt = 0; mt < 2; mt++) {
            #pragma unroll
            for (int half = 0; half < 2; half++) {
                int m = rbase + mt * 16 + half * 8;
                if (m >= BQn) continue;
                float4 q = qb[mt][half];
                float qx0 = q.x - 0.5f * q.z, qy0 = q.y - 0.5f * q.w;
                float qx1 = q.x + 0.5f * q.z, qy1 = q.y + 0.5f * q.w;
                float qarea = q.z * q.w;

                float r2[2];
                #pragma unroll
                for (int u = 0; u < 2; u++) {
                    float4 tc = u ? tc1 : tc0;
                    float4 tk = u ? tk1 : tk0;
                    float tarea = u ? ta1 : ta0;
                    float l1 = fabsf(q.x - tc.x) + fabsf(q.y - tc.y) +
                               fabsf(q.z - tc.z) + fabsf(q.w - tc.w);
                    float ltx = fmaxf(qx0, tk.x), lty = fmaxf(qy0, tk.y);
                    float rbx = fminf(qx1, tk.z), rby = fminf(qy1, tk.w);
                    float iw = fmaxf(rbx - ltx, 0.f), ih = fmaxf(rby - lty, 0.f);
                    float inter = iw * ih;
                    float uni = qarea + tarea - inter;
                    float ex0 = fminf(qx0, tk.x), ey0 = fminf(qy0, tk.y);
                    float ex1 = fmaxf(qx1, tk.z), ey1 = fmaxf(qy1, tk.w);
                    float areaE = (ex1 - ex0) * (ey1 - ey0);
                    // giou = inter/uni - (areaE-uni)/areaE, single divide:
                    float num = inter * areaE - uni * areaE + uni * uni;
                    float giou = __fdividef(num, uni * areaE);
                    float cls = acc[mt][nt][half * 2 + u];
                    r2[u] = 5.0f * l1 + CLS_SCALE * cls - 2.0f * giou;
                }
                *(float2*)(outp + (size_t)m * BTn + n0 + nl) = make_float2(r2[0], r2[1]);
            }
        }
    }
}

// ---------------- launcher ----------------
extern "C" void kernel_launch(void* const* d_in, const int* in_sizes, int n_in,
                              void* d_out, int out_size) {
    const float* logits       = (const float*)d_in[0];
    const float* pred_boxes   = (const float*)d_in[1];
    const float* label_maps   = (const float*)d_in[2];
    const float* boxes        = (const float*)d_in[3];
    const int*   class_labels = (const int*)d_in[4];
    float* out = (float*)d_out;

    cudaFuncSetAttribute(cost_kernel, cudaFuncAttributeMaxDynamicSharedMemorySize, DYNSMEM);

    prep_kernel<<<FEAT_BLOCKS + BTn, 256>>>(logits, label_maps, boxes, class_labels);
    cost_kernel<<<dim3(BTn / BN, MPAD / BM), 256, DYNSMEM>>>(pred_boxes, out);
}